// round 9
// baseline (speedup 1.0000x reference)
#include <cuda_runtime.h>
#include <cuda_fp16.h>
#include <cstdint>

// Grouped GEMM out[16384,4096]: 8 groups of [2048x4096] @ w[g][4096x4096], fp32 io.
// Pass 1: fp32 -> fp16 scratch (DRAM-bound ~81%, ~175us).
// Pass 2: fp16 HMMA m16n8k16, 128x128 tile, BK=64, 3-stage cp.async ring,
// 2 CTAs/SM. Round 8: PERSISTENT CTAs with a continuous k-counter so the
// pipeline never drains across tile boundaries (epilogue overlaps next tile's
// fill) -- removes ~14 waves of prologue/drain dead time.

#define TOK   16384
#define INF   4096
#define OUTF  4096
#define NG    8

#define BM    128
#define BN    128
#define BK    64
#define KTPT  (INF / BK)          // 64 k-tiles per tile
#define NTILES ((TOK / BM) * (OUTF / BN))   // 4096
#define NTC   (OUTF / BN)         // 32 n-tiles

#define SAH   72                  // A smem row stride (halves): 144B (bank step +4)
#define SBH   136                 // B smem row stride (halves): 272B (bank step +4)
#define A_BYTES (BM * SAH * 2)    // 18432
#define B_BYTES (BK * SBH * 2)    // 17408
#define STAGE_BYTES (A_BYTES + B_BYTES)       // 35840
#define STAGES 3
#define SMEM_BYTES (STAGES * STAGE_BYTES)     // 107520 -> 2 CTAs/SM
#define NTHREADS 256

__device__ __align__(16) __half g_xh[(size_t)TOK * INF];
__device__ __align__(16) __half g_wh[(size_t)NG * INF * OUTF];

// ---------------- pass 1: fp32 -> fp16 ----------------
__global__ void cvt_f32_f16(const float* __restrict__ src, __half* __restrict__ dst,
                            size_t n8) {
    size_t i = (size_t)blockIdx.x * blockDim.x + threadIdx.x;
    const size_t stride = (size_t)gridDim.x * blockDim.x;
    for (; i < n8; i += stride) {
        float4 v0 = reinterpret_cast<const float4*>(src)[2 * i];
        float4 v1 = reinterpret_cast<const float4*>(src)[2 * i + 1];
        __half2 h0 = __floats2half2_rn(v0.x, v0.y);
        __half2 h1 = __floats2half2_rn(v0.z, v0.w);
        __half2 h2 = __floats2half2_rn(v1.x, v1.y);
        __half2 h3 = __floats2half2_rn(v1.z, v1.w);
        uint4 u;
        u.x = *reinterpret_cast<uint32_t*>(&h0);
        u.y = *reinterpret_cast<uint32_t*>(&h1);
        u.z = *reinterpret_cast<uint32_t*>(&h2);
        u.w = *reinterpret_cast<uint32_t*>(&h3);
        reinterpret_cast<uint4*>(dst)[i] = u;
    }
}

// ---------------- pass 2: fp16 HMMA GEMM ----------------
__device__ __forceinline__ uint32_t smem_u32(const void* p) {
    uint32_t a;
    asm("{ .reg .u64 t; cvta.to.shared.u64 t, %1; cvt.u32.u64 %0, t; }"
        : "=r"(a) : "l"(p));
    return a;
}

#define CPA16(dst, src) \
    asm volatile("cp.async.cg.shared.global [%0], [%1], 16;" :: "r"(dst), "l"(src))

#define LDSM_X4(r0, r1, r2, r3, a)                                              \
    asm volatile("ldmatrix.sync.aligned.m8n8.x4.shared.b16 {%0,%1,%2,%3}, [%4];" \
                 : "=r"(r0), "=r"(r1), "=r"(r2), "=r"(r3) : "r"(a))

#define LDSM_X4T(r0, r1, r2, r3, a)                                                   \
    asm volatile("ldmatrix.sync.aligned.m8n8.x4.trans.shared.b16 {%0,%1,%2,%3}, [%4];" \
                 : "=r"(r0), "=r"(r1), "=r"(r2), "=r"(r3) : "r"(a))

__device__ __forceinline__ void mma16816(float* d, const uint32_t* a, const uint32_t* b) {
    asm volatile(
        "mma.sync.aligned.m16n8k16.row.col.f32.f16.f16.f32 "
        "{%0,%1,%2,%3}, {%4,%5,%6,%7}, {%8,%9}, {%0,%1,%2,%3};"
        : "+f"(d[0]), "+f"(d[1]), "+f"(d[2]), "+f"(d[3])
        : "r"(a[0]), "r"(a[1]), "r"(a[2]), "r"(a[3]), "r"(b[0]), "r"(b[1]));
}

extern "C" __global__ void __launch_bounds__(NTHREADS, 2)
grouped_gemm_f16(float* __restrict__ out) {
    extern __shared__ char sm[];
    const uint32_t smb = smem_u32(sm);

    const int t = threadIdx.x;
    const int lane = t & 31;
    const int wid = t >> 5;          // 8 warps: 2 (m) x 4 (n)
    const int wm = wid & 1;          // 64-row warp tile
    const int wn = wid >> 1;         // 32-col warp tile

    const int bid = blockIdx.x;
    const int G   = gridDim.x;
    const int my_tiles = (NTILES - bid + G - 1) / G;
    if (my_tiles <= 0) return;
    const int total_k = my_tiles * KTPT;

    // load one k-tile addressed by CONTINUOUS counter kc (tile j = kc/64)
    auto load_tile = [&](int kc) {
        const int tile = bid + (kc >> 6) * G;
        const int kt = kc & (KTPT - 1);
        const int nt = tile & (NTC - 1);
        const int mt = tile >> 5;
        const int g  = mt >> 4;
        const __half* xg = g_xh + (size_t)mt * BM * INF;
        const __half* wg = g_wh + (size_t)g * INF * OUTF + (size_t)nt * BN;
        const uint32_t sb = smb + (uint32_t)(kc % STAGES) * STAGE_BYTES;
#pragma unroll
        for (int i = 0; i < 4; i++) {           // A: 1024 x 16B; id = row*8 + kc
            int id = t + i * NTHREADS;
            int row = id >> 3, kk = id & 7;
            CPA16(sb + (uint32_t)row * (SAH * 2) + (uint32_t)kk * 16,
                  xg + (size_t)row * INF + (size_t)kt * BK + kk * 8);
        }
#pragma unroll
        for (int i = 0; i < 4; i++) {           // B: 1024 x 16B; id = k*16 + nc
            int id = t + i * NTHREADS;
            int k = id >> 4, nc = id & 15;
            CPA16(sb + A_BYTES + (uint32_t)k * (SBH * 2) + (uint32_t)nc * 16,
                  wg + (size_t)((size_t)kt * BK + k) * OUTF + nc * 8);
        }
        asm volatile("cp.async.commit_group;" ::: "memory");
    };

    load_tile(0);
    load_tile(1);

    // ldmatrix per-lane base byte offsets within a stage
    const uint32_t aOff =
        (uint32_t)(wm * 64 + (lane & 7) + ((lane >> 3) & 1) * 8) * (SAH * 2) +
        (uint32_t)((lane >> 4) & 1) * 16;
    const uint32_t bOff = A_BYTES +
        (uint32_t)((lane & 7) + ((lane >> 3) & 1) * 8) * (SBH * 2) +
        (uint32_t)(wn * 32 + ((lane >> 4) & 1) * 8) * 2;

    int kc = 0;
    for (int ti = 0; ti < my_tiles; ti++) {
        float acc[4][4][4];
#pragma unroll
        for (int mi = 0; mi < 4; mi++)
#pragma unroll
            for (int ni = 0; ni < 4; ni++)
#pragma unroll
                for (int q = 0; q < 4; q++) acc[mi][ni][q] = 0.0f;

        for (int kt = 0; kt < KTPT; kt++, kc++) {
            asm volatile("cp.async.wait_group 1;" ::: "memory");  // group kc done
            __syncthreads();   // tile visible; stage (kc+2)%3's readers (kc-1) done

            if (kc + 2 < total_k) load_tile(kc + 2);
            else asm volatile("cp.async.commit_group;" ::: "memory");

            const uint32_t stage = smb + (uint32_t)(kc % STAGES) * STAGE_BYTES;

#pragma unroll
            for (int ks = 0; ks < 4; ks++) {   // BK=64 -> 4 x k16
                uint32_t a[4][4], b[2][4];
#pragma unroll
                for (int np = 0; np < 2; np++)
                    LDSM_X4T(b[np][0], b[np][1], b[np][2], b[np][3],
                             stage + bOff + (uint32_t)ks * (16 * SBH * 2) +
                                 (uint32_t)np * 32);
#pragma unroll
                for (int mi = 0; mi < 4; mi++)
                    LDSM_X4(a[mi][0], a[mi][1], a[mi][2], a[mi][3],
                            stage + aOff + (uint32_t)mi * (16 * SAH * 2) +
                                (uint32_t)ks * 32);
#pragma unroll
                for (int mi = 0; mi < 4; mi++)
#pragma unroll
                    for (int np = 0; np < 2; np++) {
                        mma16816(acc[mi][2 * np],     a[mi], &b[np][0]);
                        mma16816(acc[mi][2 * np + 1], a[mi], &b[np][2]);
                    }
            }
        }

        // epilogue for tile ti (overlaps the already-issued next-tile loads)
        const int tile = bid + ti * G;
        const int nt = tile & (NTC - 1);
        const int mt = tile >> 5;
        const int r0 = mt * BM + wm * 64 + (lane >> 2);
        const int c0 = nt * BN + wn * 32 + 2 * (lane & 3);
#pragma unroll
        for (int mi = 0; mi < 4; mi++)
#pragma unroll
            for (int ni = 0; ni < 4; ni++) {
                size_t base = (size_t)(r0 + mi * 16) * OUTF + c0 + ni * 8;
                *reinterpret_cast<float2*>(out + base) =
                    make_float2(acc[mi][ni][0], acc[mi][ni][1]);
                *reinterpret_cast<float2*>(out + base + 8 * OUTF) =
                    make_float2(acc[mi][ni][2], acc[mi][ni][3]);
            }
    }
}

extern "C" void kernel_launch(void* const* d_in, const int* in_sizes, int n_in,
                              void* d_out, int out_size) {
    const float* x = (const float*)d_in[0];
    const float* w = (const float*)d_in[1];
    float* out = (float*)d_out;

    __half* xh = nullptr;
    __half* wh = nullptr;
    cudaGetSymbolAddress((void**)&xh, g_xh);
    cudaGetSymbolAddress((void**)&wh, g_wh);

    cvt_f32_f16<<<4096, 256>>>(x, xh, (size_t)TOK * INF / 8);
    cvt_f32_f16<<<8192, 256>>>(w, wh, (size_t)NG * INF * OUTF / 8);

    int nsm = 148;
    cudaDeviceGetAttribute(&nsm, cudaDevAttrMultiProcessorCount, 0);

    cudaFuncSetAttribute(grouped_gemm_f16,
                         cudaFuncAttributeMaxDynamicSharedMemorySize, SMEM_BYTES);
    grouped_gemm_f16<<<2 * nsm, NTHREADS, SMEM_BYTES>>>(out);
}